// round 15
// baseline (speedup 1.0000x reference)
#include <cuda_runtime.h>
#include <cuda_fp16.h>
#include <cstdint>

// ---------------------------------------------------------------------------
// Problem constants
// ---------------------------------------------------------------------------
#define VOCAB 10000
#define VPAD  10240          // 40 * 256
#define EMB   64
#define HID   128
#define BATCH 32
#define TLEN  256
#define ROWS  (BATCH * TLEN) // 8192

// ---------------------------------------------------------------------------
// Device scratch (no allocation allowed)
// ---------------------------------------------------------------------------
__device__ __align__(16) float   g_xw[ROWS * HID];       // 4 MB
__device__ __align__(16) __half  g_rnn_h[ROWS * HID];    // 2 MB
__device__ __align__(16) __half  g_wdt_h[VPAD * HID];    // 2.6 MB
__device__ __align__(16) float   g_hst[BATCH * HID];     // scan state hand-off

// ---------------------------------------------------------------------------
// PTX helpers (plain-target instructions only; no tcgen05)
// ---------------------------------------------------------------------------
__device__ __forceinline__ uint32_t smem_u32(const void* p) {
    uint32_t a;
    asm("{ .reg .u64 t; cvta.to.shared.u64 t, %1; cvt.u32.u64 %0, t; }" : "=r"(a) : "l"(p));
    return a;
}
__device__ __forceinline__ void ldsm_x4(uint32_t* r, uint32_t addr) {
    asm volatile("ldmatrix.sync.aligned.m8n8.x4.shared.b16 {%0,%1,%2,%3}, [%4];"
                 : "=r"(r[0]), "=r"(r[1]), "=r"(r[2]), "=r"(r[3]) : "r"(addr));
}
__device__ __forceinline__ void mma16816(float* c, const uint32_t* a,
                                         uint32_t b0, uint32_t b1) {
    asm volatile("mma.sync.aligned.m16n8k16.row.col.f32.f16.f16.f32 "
                 "{%0,%1,%2,%3}, {%4,%5,%6,%7}, {%8,%9}, {%0,%1,%2,%3};"
                 : "+f"(c[0]), "+f"(c[1]), "+f"(c[2]), "+f"(c[3])
                 : "r"(a[0]), "r"(a[1]), "r"(a[2]), "r"(a[3]), "r"(b0), "r"(b1));
}
__device__ __forceinline__ void cp16(uint32_t dst, const void* src) {
    asm volatile("cp.async.cg.shared.global [%0], [%1], 16;" :: "r"(dst), "l"(src));
}
#define CP_COMMIT()  asm volatile("cp.async.commit_group;" ::: "memory")
#define CP_WAIT(N)   asm volatile("cp.async.wait_group %0;" :: "n"(N) : "memory")

// packed f32x2 ops
__device__ __forceinline__ void fma2(unsigned long long& acc,
                                     unsigned long long a, unsigned long long b) {
    asm("fma.rn.f32x2 %0, %1, %2, %0;" : "+l"(acc) : "l"(a), "l"(b));
}
__device__ __forceinline__ unsigned long long add2(unsigned long long a,
                                                   unsigned long long b) {
    unsigned long long d;
    asm("add.rn.f32x2 %0, %1, %2;" : "=l"(d) : "l"(a), "l"(b));
    return d;
}
__device__ __forceinline__ unsigned long long pack2(float x, float y) {
    unsigned long long p;
    asm("mov.b64 %0, {%1, %2};" : "=l"(p) : "f"(x), "f"(y));
    return p;
}
__device__ __forceinline__ void unpack2(unsigned long long p, float& x, float& y) {
    asm("mov.b64 {%0, %1}, %2;" : "=f"(x), "=f"(y) : "l"(p));
}

// ---------------------------------------------------------------------------
// Kernel 1: transpose Wd -> WdT[v][k] fp16, zero-padded to VPAD
// ---------------------------------------------------------------------------
__global__ void k_wdt(const float* __restrict__ Wd) {
    __shared__ float tile[32][33];
    int n0 = blockIdx.x * 32;   // vocab
    int k0 = blockIdx.y * 32;   // hid
    int tx = threadIdx.x, ty = threadIdx.y;  // 32 x 8
    #pragma unroll
    for (int i = 0; i < 32; i += 8) {
        int k = k0 + ty + i, n = n0 + tx;
        tile[ty + i][tx] = (n < VOCAB) ? Wd[(size_t)k * VOCAB + n] : 0.f;
    }
    __syncthreads();
    #pragma unroll
    for (int i = 0; i < 32; i += 8) {
        int n = n0 + ty + i, k = k0 + tx;
        g_wdt_h[n * HID + k] = __float2half(tile[tx][ty + i]);
    }
}

// ---------------------------------------------------------------------------
// Kernel 2: embed + input projection, with inline ids-dtype detection
// (samples odd 32-bit words of the first 256 id slots; if ids are int64
// with values < 2^31 these are all zero). 32 timesteps per 256-thread block;
// W in 64 registers; 4-row ILP; float4 xs reads.
// ---------------------------------------------------------------------------
__global__ void __launch_bounds__(256, 1) k_embed(const void* __restrict__ ids_raw,
                                                  const float* __restrict__ emb,
                                                  const float* __restrict__ W,
                                                  const float* __restrict__ b,
                                                  int t_base, int n32) {
    __shared__ __align__(16) float xs[32][EMB];   // 8 KB
    __shared__ int s_any;
    int tid = threadIdx.x;
    int j   = tid & 127;       // hid unit
    int hh  = tid >> 7;        // row half (0/1)

    // inline dtype detect (first 512 words are in-bounds for either dtype)
    if (tid == 0) s_any = 0;
    unsigned int xw_ = ((const unsigned int*)ids_raw)[2 * tid + 1];
    __syncthreads();
    if (xw_) atomicOr(&s_any, 1);

    float wreg[EMB];
    #pragma unroll
    for (int e = 0; e < EMB; e++) wreg[e] = W[e * HID + j];
    __syncthreads();
    int is64 = (s_any == 0);

    int bb   = blockIdx.x / n32;
    int tloc = (blockIdx.x % n32) * 32;
    int r0   = bb * TLEN + t_base + tloc;

    for (int p = tid; p < 32 * EMB; p += 256) {
        int ri = p >> 6, e = p & 63;
        long long id = is64 ? ((const long long*)ids_raw)[r0 + ri]
                            : (long long)((const int*)ids_raw)[r0 + ri];
        xs[ri][e] = emb[id * EMB + e];
    }
    __syncthreads();

    float bj = b[j];
    #pragma unroll
    for (int rg = 0; rg < 4; rg++) {
        int row = hh * 16 + rg * 4;
        float a0 = bj, a1 = bj, a2 = bj, a3 = bj;
        #pragma unroll
        for (int e = 0; e < EMB; e += 4) {
            float4 x0 = *(const float4*)&xs[row + 0][e];
            float4 x1 = *(const float4*)&xs[row + 1][e];
            float4 x2 = *(const float4*)&xs[row + 2][e];
            float4 x3 = *(const float4*)&xs[row + 3][e];
            a0 += x0.x * wreg[e] + x0.y * wreg[e + 1] + x0.z * wreg[e + 2] + x0.w * wreg[e + 3];
            a1 += x1.x * wreg[e] + x1.y * wreg[e + 1] + x1.z * wreg[e + 2] + x1.w * wreg[e + 3];
            a2 += x2.x * wreg[e] + x2.y * wreg[e + 1] + x2.z * wreg[e + 2] + x2.w * wreg[e + 3];
            a3 += x3.x * wreg[e] + x3.y * wreg[e + 1] + x3.z * wreg[e + 2] + x3.w * wreg[e + 3];
        }
        g_xw[(r0 + row + 0) * HID + j] = a0;
        g_xw[(r0 + row + 1) * HID + j] = a1;
        g_xw[(r0 + row + 2) * HID + j] = a2;
        g_xw[(r0 + row + 3) * HID + j] = a3;
    }
}

// ---------------------------------------------------------------------------
// Kernel 3 (v2): RNN scan chunk, k-split over 256 threads (2 warps/SMSP).
// Thread (j, p): partial_p[j] = sum over k in [64p, 64p+64) of U[k][j]*h[k].
// Halves combine through SMEM; p=1 threads handle the fp16 emission off the
// critical path. Single h buffer; 2 barriers/step. State via g_hst (fp32).
// ---------------------------------------------------------------------------
__global__ void __launch_bounds__(256, 1) k_scan(const float* __restrict__ U,
                                                 int t0, int tch) {
    __shared__ __align__(16) float h[HID];
    __shared__ float ps[HID];
    int bb  = blockIdx.x;
    int tid = threadIdx.x;
    int j   = tid & 127;
    int p   = tid >> 7;

    unsigned long long u2[32];
    #pragma unroll
    for (int q = 0; q < 32; q++)
        u2[q] = pack2(U[(p * 64 + 2 * q) * HID + j],
                      U[(p * 64 + 2 * q + 1) * HID + j]);

    if (p == 0) h[j] = (t0 == 0) ? 0.f : g_hst[bb * HID + j];
    __syncthreads();

    const float* xwp  = g_xw    + ((size_t)bb * TLEN + t0) * HID + j;
    __half*      outp = g_rnn_h + ((size_t)bb * TLEN + t0) * HID + j;
    float xw_cur = (p == 0) ? xwp[0] : 0.f;

    #pragma unroll 1
    for (int t = 0; t < tch; t++) {
        unsigned long long a[4];
        a[0] = pack2(xw_cur, 0.f);
        a[1] = 0ull; a[2] = 0ull; a[3] = 0ull;

        const ulonglong2* hp = (const ulonglong2*)&h[p * 64];
        float emit_val = (p && t) ? h[j] : 0.f;     // step t-1 value
        #pragma unroll
        for (int i = 0; i < 16; i++) {
            ulonglong2 hv = hp[i];
            fma2(a[(2 * i) & 3],     u2[2 * i],     hv.x);
            fma2(a[(2 * i + 1) & 3], u2[2 * i + 1], hv.y);
        }
        unsigned long long s = add2(add2(a[0], a[1]), add2(a[2], a[3]));
        float zx, zy;
        unpack2(s, zx, zy);
        float partial = zx + zy;

        if (p) {
            ps[j] = partial;
            if (t) outp[(t - 1) * HID] = __float2half(emit_val);
        }
        __syncthreads();                   // partials visible; all h reads done

        if (p == 0) {
            float z = partial + ps[j];
            float e = __expf(2.f * z);
            float hval = 1.f - __fdividef(2.f, e + 1.f);
            h[j] = hval;
            xw_cur = (t < tch - 1) ? xwp[(t + 1) * HID] : 0.f;
        }
        __syncthreads();                   // h[t] visible to all
    }

    if (p) outp[(tch - 1) * HID] = __float2half(h[j]);
    else   g_hst[bb * HID + j] = h[j];
}

// ---------------------------------------------------------------------------
// Kernel 4: output GEMM chunk (timesteps [t0, t0+TL) of every batch).
// Templated on TL (16/32/64): A-tile 128 rows = (128/TL) batches' segments.
// B (v-tile 256) resident, 2 A-tiles per CTA double-buffered.
// ---------------------------------------------------------------------------
#define SB_BYTES   65536                 // 256 rows x 256B (fp16)
#define SA_BYTES   32768                 // per stage: 128 rows x 256B
#define N_TILES    2
#define SM_TOTAL   (SB_BYTES + N_TILES * SA_BYTES)   // 128 KB

template<int TL>
__device__ __forceinline__ void gemm_load_a(uint32_t sAbuf, int bstart, int t0,
                                            int tid) {
    #pragma unroll
    for (int i = tid; i < 2048; i += 256) {       // 128 rows x 16 chunks
        int row = i >> 4, ch = i & 15;
        int gr = (bstart + row / TL) * TLEN + t0 + (row & (TL - 1));
        uint32_t dst = sAbuf + row * 256 + ((ch ^ (row & 7)) << 4);
        cp16(dst, g_rnn_h + (size_t)gr * HID + ch * 8);
    }
}

template<int TL>
__global__ void __launch_bounds__(256, 1) k_gemm(const float* __restrict__ bd,
                                                 float* __restrict__ out, int t0) {
    extern __shared__ char smem[];
    uint32_t sB  = smem_u32(smem);
    uint32_t sA0 = sB + SB_BYTES;

    int tid  = threadIdx.x;
    int wid  = tid >> 5;
    int lane = tid & 31;
    int v0   = blockIdx.x * 256;
    const int BPT = 128 / TL;               // batches per A-tile
    int bg   = blockIdx.y * (N_TILES * BPT);

    // ---- prologue: B (resident) + A0 in group 0; A1 in group 1 ----
    #pragma unroll
    for (int i = tid; i < 4096; i += 256) {       // B: 256 rows x 16 chunks
        int row = i >> 4, ch = i & 15;
        uint32_t dst = sB + row * 256 + ((ch ^ (row & 7)) << 4);
        cp16(dst, g_wdt_h + (size_t)(v0 + row) * HID + ch * 8);
    }
    gemm_load_a<TL>(sA0, bg, t0, tid);
    CP_COMMIT();
    gemm_load_a<TL>(sA0 + SA_BYTES, bg + BPT, t0, tid);
    CP_COMMIT();

    int wm = wid & 1;          // 2 warps over the 128 A rows (64 each)
    int wn = wid >> 1;         // 4 warps over v (64 each)
    int rA  = ((lane >> 3) & 1) * 8 + (lane & 7);
    int kcA = lane >> 4;
    int rB  = ((lane >> 4) & 1) * 8 + (lane & 7);
    int kcB = (lane >> 3) & 1;
    int lx  = lane & 7;

    #pragma unroll 1
    for (int it = 0; it < N_TILES; it++) {
        if (it == 0) { CP_WAIT(1); } else { CP_WAIT(0); }
        __syncthreads();

        uint32_t sAb = sA0 + it * SA_BYTES;
        int btile = bg + it * BPT;            // first batch of this A-tile

        float c[4][8][4];
        #pragma unroll
        for (int mb = 0; mb < 4; mb++)
            #pragma unroll
            for (int nb = 0; nb < 8; nb++)
                #pragma unroll
                for (int q = 0; q < 4; q++) c[mb][nb][q] = 0.f;

        uint32_t aBase = sAb + (uint32_t)(wm * 64 + rA) * 256;
        uint32_t bBase = sB  + (uint32_t)(wn * 64 + rB) * 256;
        #pragma unroll 1
        for (int ks = 0; ks < 8; ks++) {
            uint32_t a[4][4], b[4][4];
            int kA = (ks * 2 + kcA) ^ lx;
            int kB = (ks * 2 + kcB) ^ lx;
            #pragma unroll
            for (int mb = 0; mb < 4; mb++)
                ldsm_x4(a[mb], aBase + (uint32_t)(mb * 16) * 256 + (kA << 4));
            #pragma unroll
            for (int nb = 0; nb < 4; nb++)
                ldsm_x4(b[nb], bBase + (uint32_t)(nb * 16) * 256 + (kB << 4));
            #pragma unroll
            for (int mb = 0; mb < 4; mb++)
                #pragma unroll
                for (int nbi = 0; nbi < 8; nbi++)
                    mma16816(c[mb][nbi], a[mb],
                             b[nbi >> 1][(nbi & 1) * 2],
                             b[nbi >> 1][(nbi & 1) * 2 + 1]);
        }
        __syncthreads();

        // ---- epilogue: bias + store ----
        #pragma unroll
        for (int nbi = 0; nbi < 8; nbi++) {
            int col = v0 + wn * 64 + nbi * 8 + (lane & 3) * 2;
            if (col < VOCAB) {
                float b0 = bd[col], b1 = bd[col + 1];
                #pragma unroll
                for (int mb = 0; mb < 4; mb++) {
                    int lr0 = wm * 64 + mb * 16;          // local A row of c[..][0]
                    int r = (btile + lr0 / TL) * TLEN + t0 + (lr0 & (TL - 1))
                          + (lane >> 2);
                    float2 lo = make_float2(c[mb][nbi][0] + b0, c[mb][nbi][1] + b1);
                    float2 hi = make_float2(c[mb][nbi][2] + b0, c[mb][nbi][3] + b1);
                    *(float2*)(out + (size_t)r * VOCAB + col) = lo;
                    *(float2*)(out + (size_t)(r + 8) * VOCAB + col) = hi;
                }
            }
        }
    }
}

// ---------------------------------------------------------------------------
// Launch: chunks (32,64,64,64,16,16). s2 = wdt; s4 = embed rest + odd gemm;
// s3 = even gemm. Each gemm gated on eWdt + its scan event.
// ---------------------------------------------------------------------------
#define NCHUNK 6

extern "C" void kernel_launch(void* const* d_in, const int* in_sizes, int n_in,
                              void* d_out, int out_size) {
    const void*  ids = d_in[0];
    const float* emb = (const float*)d_in[1];
    const float* W   = (const float*)d_in[2];
    const float* U   = (const float*)d_in[3];
    const float* b   = (const float*)d_in[4];
    const float* Wd  = (const float*)d_in[5];
    const float* bd  = (const float*)d_in[6];
    float* out = (float*)d_out;

    static cudaStream_t s2 = nullptr, s3 = nullptr, s4 = nullptr;
    static cudaEvent_t eFork = nullptr, eWdt = nullptr,
                       eEr1 = nullptr, eEr2 = nullptr,
                       eS[NCHUNK] = {}, eG3 = nullptr, eG4 = nullptr;
    if (!s2) {
        cudaStreamCreateWithFlags(&s2, cudaStreamNonBlocking);
        cudaStreamCreateWithFlags(&s3, cudaStreamNonBlocking);
        cudaStreamCreateWithFlags(&s4, cudaStreamNonBlocking);
        cudaEventCreateWithFlags(&eFork, cudaEventDisableTiming);
        cudaEventCreateWithFlags(&eWdt,  cudaEventDisableTiming);
        cudaEventCreateWithFlags(&eEr1,  cudaEventDisableTiming);
        cudaEventCreateWithFlags(&eEr2,  cudaEventDisableTiming);
        for (int i = 0; i < NCHUNK; i++)
            cudaEventCreateWithFlags(&eS[i], cudaEventDisableTiming);
        cudaEventCreateWithFlags(&eG3, cudaEventDisableTiming);
        cudaEventCreateWithFlags(&eG4, cudaEventDisableTiming);
        cudaFuncSetAttribute(k_gemm<64>, cudaFuncAttributeMaxDynamicSharedMemorySize, SM_TOTAL);
        cudaFuncSetAttribute(k_gemm<32>, cudaFuncAttributeMaxDynamicSharedMemorySize, SM_TOTAL);
        cudaFuncSetAttribute(k_gemm<16>, cudaFuncAttributeMaxDynamicSharedMemorySize, SM_TOTAL);
    }

    cudaEventRecord(eFork, 0);

    // s2: Wd transpose
    cudaStreamWaitEvent(s2, eFork, 0);
    k_wdt<<<dim3(VPAD / 32, HID / 32), dim3(32, 8), 0, s2>>>(Wd);
    cudaEventRecord(eWdt, s2);

    // main: embed head (t < 32) — gates scan chunk 0
    k_embed<<<BATCH, 256>>>(ids, emb, W, b, 0, 1);

    // s4: embed rest (starts at graph origin; no detect dependency)
    cudaStreamWaitEvent(s4, eFork, 0);
    k_embed<<<BATCH * 2, 256, 0, s4>>>(ids, emb, W, b, 32, 2);    // t in [32,96)
    cudaEventRecord(eEr1, s4);
    k_embed<<<BATCH * 5, 256, 0, s4>>>(ids, emb, W, b, 96, 5);    // t in [96,256)
    cudaEventRecord(eEr2, s4);

    // main: scan chunks 32,64,64,64,16,16
    static const int t0s[NCHUNK]  = {0, 32, 96, 160, 224, 240};
    static const int tchs[NCHUNK] = {32, 64, 64, 64, 16, 16};
    for (int q = 0; q < NCHUNK; q++) {
        if (q == 1) cudaStreamWaitEvent(0, eEr1, 0);
        if (q == 2) cudaStreamWaitEvent(0, eEr2, 0);
        k_scan<<<BATCH, 256>>>(U, t0s[q], tchs[q]);
        cudaEventRecord(eS[q], 0);
    }

    // gemm chunks: even on s3, odd on s4; each gated on eWdt + its scan
    cudaStreamWaitEvent(s3, eWdt, 0);
    cudaStreamWaitEvent(s4, eWdt, 0);

    cudaStreamWaitEvent(s3, eS[0], 0);
    k_gemm<32><<<dim3(VPAD / 256, 4), 256, SM_TOTAL, s3>>>(bd, out, t0s[0]);
    cudaStreamWaitEvent(s4, eS[1], 0);
    k_gemm<64><<<dim3(VPAD / 256, 8), 256, SM_TOTAL, s4>>>(bd, out, t0s[1]);
    cudaStreamWaitEvent(s3, eS[2], 0);
    k_gemm<64><<<dim3(VPAD / 256, 8), 256, SM_TOTAL, s3>>>(bd, out, t0s[2]);
    cudaStreamWaitEvent(s4, eS[3], 0);
    k_gemm<64><<<dim3(VPAD / 256, 8), 256, SM_TOTAL, s4>>>(bd, out, t0s[3]);
    cudaStreamWaitEvent(s3, eS[4], 0);
    k_gemm<16><<<dim3(VPAD / 256, 2), 256, SM_TOTAL, s3>>>(bd, out, t0s[4]);
    cudaStreamWaitEvent(s4, eS[5], 0);
    k_gemm<16><<<dim3(VPAD / 256, 2), 256, SM_TOTAL, s4>>>(bd, out, t0s[5]);

    cudaEventRecord(eG3, s3);
    cudaEventRecord(eG4, s4);
    cudaStreamWaitEvent(0, eG3, 0);
    cudaStreamWaitEvent(0, eG4, 0);
}

// round 16
// speedup vs baseline: 1.0619x; 1.0619x over previous
#include <cuda_runtime.h>
#include <cuda_fp16.h>
#include <cstdint>

// ---------------------------------------------------------------------------
// Problem constants
// ---------------------------------------------------------------------------
#define VOCAB 10000
#define VPAD  10240          // 40 * 256
#define EMB   64
#define HID   128
#define BATCH 32
#define TLEN  256
#define ROWS  (BATCH * TLEN) // 8192

// ---------------------------------------------------------------------------
// Device scratch (no allocation allowed)
// ---------------------------------------------------------------------------
__device__ __align__(16) float   g_xw[ROWS * HID];       // 4 MB
__device__ __align__(16) __half  g_rnn_h[ROWS * HID];    // 2 MB
__device__ __align__(16) __half  g_wdt_h[VPAD * HID];    // 2.6 MB
__device__ __align__(16) float   g_hst[BATCH * HID];     // scan state hand-off

// ---------------------------------------------------------------------------
// PTX helpers (plain-target instructions only; no tcgen05)
// ---------------------------------------------------------------------------
__device__ __forceinline__ uint32_t smem_u32(const void* p) {
    uint32_t a;
    asm("{ .reg .u64 t; cvta.to.shared.u64 t, %1; cvt.u32.u64 %0, t; }" : "=r"(a) : "l"(p));
    return a;
}
__device__ __forceinline__ void ldsm_x4(uint32_t* r, uint32_t addr) {
    asm volatile("ldmatrix.sync.aligned.m8n8.x4.shared.b16 {%0,%1,%2,%3}, [%4];"
                 : "=r"(r[0]), "=r"(r[1]), "=r"(r[2]), "=r"(r[3]) : "r"(addr));
}
__device__ __forceinline__ void mma16816(float* c, const uint32_t* a,
                                         uint32_t b0, uint32_t b1) {
    asm volatile("mma.sync.aligned.m16n8k16.row.col.f32.f16.f16.f32 "
                 "{%0,%1,%2,%3}, {%4,%5,%6,%7}, {%8,%9}, {%0,%1,%2,%3};"
                 : "+f"(c[0]), "+f"(c[1]), "+f"(c[2]), "+f"(c[3])
                 : "r"(a[0]), "r"(a[1]), "r"(a[2]), "r"(a[3]), "r"(b0), "r"(b1));
}
__device__ __forceinline__ void cp16(uint32_t dst, const void* src) {
    asm volatile("cp.async.cg.shared.global [%0], [%1], 16;" :: "r"(dst), "l"(src));
}
#define CP_COMMIT()  asm volatile("cp.async.commit_group;" ::: "memory")
#define CP_WAIT(N)   asm volatile("cp.async.wait_group %0;" :: "n"(N) : "memory")

// packed f32x2 ops
__device__ __forceinline__ void fma2(unsigned long long& acc,
                                     unsigned long long a, unsigned long long b) {
    asm("fma.rn.f32x2 %0, %1, %2, %0;" : "+l"(acc) : "l"(a), "l"(b));
}
__device__ __forceinline__ unsigned long long add2(unsigned long long a,
                                                   unsigned long long b) {
    unsigned long long d;
    asm("add.rn.f32x2 %0, %1, %2;" : "=l"(d) : "l"(a), "l"(b));
    return d;
}
__device__ __forceinline__ unsigned long long pack2(float x, float y) {
    unsigned long long p;
    asm("mov.b64 %0, {%1, %2};" : "=l"(p) : "f"(x), "f"(y));
    return p;
}
__device__ __forceinline__ void unpack2(unsigned long long p, float& x, float& y) {
    asm("mov.b64 {%0, %1}, %2;" : "=f"(x), "=f"(y) : "l"(p));
}

// ---------------------------------------------------------------------------
// Kernel 1: transpose Wd -> WdT[v][k] fp16, zero-padded to VPAD
// ---------------------------------------------------------------------------
__global__ void k_wdt(const float* __restrict__ Wd) {
    __shared__ float tile[32][33];
    int n0 = blockIdx.x * 32;   // vocab
    int k0 = blockIdx.y * 32;   // hid
    int tx = threadIdx.x, ty = threadIdx.y;  // 32 x 8
    #pragma unroll
    for (int i = 0; i < 32; i += 8) {
        int k = k0 + ty + i, n = n0 + tx;
        tile[ty + i][tx] = (n < VOCAB) ? Wd[(size_t)k * VOCAB + n] : 0.f;
    }
    __syncthreads();
    #pragma unroll
    for (int i = 0; i < 32; i += 8) {
        int n = n0 + ty + i, k = k0 + tx;
        g_wdt_h[n * HID + k] = __float2half(tile[tx][ty + i]);
    }
}

// ---------------------------------------------------------------------------
// Kernel 2: embed + input projection, with inline ids-dtype detection
// (samples odd 32-bit words of the first 256 id slots; int64 ids < 2^31
// have these all zero). 32 timesteps per 256-thread block; W in 64 regs;
// 4-row ILP accumulators; float4 xs reads.
// ---------------------------------------------------------------------------
__global__ void __launch_bounds__(256, 1) k_embed(const void* __restrict__ ids_raw,
                                                  const float* __restrict__ emb,
                                                  const float* __restrict__ W,
                                                  const float* __restrict__ b,
                                                  int t_base, int n32) {
    __shared__ __align__(16) float xs[32][EMB];   // 8 KB
    __shared__ int s_any;
    int tid = threadIdx.x;
    int j   = tid & 127;       // hid unit
    int hh  = tid >> 7;        // row half (0/1)

    // inline dtype detect (first 512 words are in-bounds for either dtype)
    if (tid == 0) s_any = 0;
    unsigned int xw_ = ((const unsigned int*)ids_raw)[2 * tid + 1];
    __syncthreads();
    if (xw_) atomicOr(&s_any, 1);

    float wreg[EMB];
    #pragma unroll
    for (int e = 0; e < EMB; e++) wreg[e] = W[e * HID + j];
    __syncthreads();
    int is64 = (s_any == 0);

    int bb   = blockIdx.x / n32;
    int tloc = (blockIdx.x % n32) * 32;
    int r0   = bb * TLEN + t_base + tloc;

    for (int p = tid; p < 32 * EMB; p += 256) {
        int ri = p >> 6, e = p & 63;
        long long id = is64 ? ((const long long*)ids_raw)[r0 + ri]
                            : (long long)((const int*)ids_raw)[r0 + ri];
        xs[ri][e] = emb[id * EMB + e];
    }
    __syncthreads();

    float bj = b[j];
    #pragma unroll
    for (int rg = 0; rg < 4; rg++) {
        int row = hh * 16 + rg * 4;
        float a0 = bj, a1 = bj, a2 = bj, a3 = bj;
        #pragma unroll
        for (int e = 0; e < EMB; e += 4) {
            float4 x0 = *(const float4*)&xs[row + 0][e];
            float4 x1 = *(const float4*)&xs[row + 1][e];
            float4 x2 = *(const float4*)&xs[row + 2][e];
            float4 x3 = *(const float4*)&xs[row + 3][e];
            a0 += x0.x * wreg[e] + x0.y * wreg[e + 1] + x0.z * wreg[e + 2] + x0.w * wreg[e + 3];
            a1 += x1.x * wreg[e] + x1.y * wreg[e + 1] + x1.z * wreg[e + 2] + x1.w * wreg[e + 3];
            a2 += x2.x * wreg[e] + x2.y * wreg[e + 1] + x2.z * wreg[e + 2] + x2.w * wreg[e + 3];
            a3 += x3.x * wreg[e] + x3.y * wreg[e + 1] + x3.z * wreg[e + 2] + x3.w * wreg[e + 3];
        }
        g_xw[(r0 + row + 0) * HID + j] = a0;
        g_xw[(r0 + row + 1) * HID + j] = a1;
        g_xw[(r0 + row + 2) * HID + j] = a2;
        g_xw[(r0 + row + 3) * HID + j] = a3;
    }
}

// ---------------------------------------------------------------------------
// Kernel 3 (v1 — proven fastest): RNN scan chunk. 1 batch/CTA, 128 thr.
// 8 independent f32x2 accumulator chains; f32x2 reduction tree; single
// barrier per step; fp16 emission after the barrier (off the critical path).
// State carried through g_hst (fp32, exact).
// ---------------------------------------------------------------------------
__global__ void __launch_bounds__(HID, 1) k_scan(const float* __restrict__ U,
                                                 int t0, int tch) {
    __shared__ __align__(16) float h[2][HID];
    int bb = blockIdx.x;
    int j  = threadIdx.x;

    unsigned long long u2[HID / 2];
    #pragma unroll
    for (int q = 0; q < HID / 2; q++)
        u2[q] = pack2(U[(2 * q) * HID + j], U[(2 * q + 1) * HID + j]);

    float h0 = (t0 == 0) ? 0.f : g_hst[bb * HID + j];
    h[0][j] = h0;
    __syncthreads();

    const float* xwp  = g_xw    + ((size_t)bb * TLEN + t0) * HID + j;
    __half*      outp = g_rnn_h + ((size_t)bb * TLEN + t0) * HID + j;
    float xw_cur = xwp[0];
    int buf = 0;
    float h_prev = 0.f;
    int   emit   = 0;

    #pragma unroll 1
    for (int t = 0; t < tch; t++) {
        float xw_next = (t < tch - 1) ? xwp[(t + 1) * HID] : 0.f;

        unsigned long long a[8];
        a[0] = pack2(xw_cur, 0.f);
        #pragma unroll
        for (int q = 1; q < 8; q++) a[q] = 0ull;

        const ulonglong2* hp = (const ulonglong2*)&h[buf][0];
        #pragma unroll
        for (int i = 0; i < 32; i++) {
            ulonglong2 hv = hp[i];
            fma2(a[(2 * i) & 7],     u2[2 * i],     hv.x);
            fma2(a[(2 * i + 1) & 7], u2[2 * i + 1], hv.y);
        }
        unsigned long long r0 = add2(a[0], a[1]);
        unsigned long long r1 = add2(a[2], a[3]);
        unsigned long long r2 = add2(a[4], a[5]);
        unsigned long long r3 = add2(a[6], a[7]);
        unsigned long long s  = add2(add2(r0, r1), add2(r2, r3));
        float zx, zy;
        unpack2(s, zx, zy);
        float z = zx + zy;

        float e = __expf(2.f * z);
        float hval = 1.f - __fdividef(2.f, e + 1.f);

        h[buf ^ 1][j] = hval;              // STS first: only thing the barrier gates
        __syncthreads();

        if (emit) outp[(t - 1) * HID] = __float2half(h_prev);
        h_prev = hval;
        emit = 1;
        buf ^= 1;
        xw_cur = xw_next;
    }
    outp[(tch - 1) * HID] = __float2half(h_prev);
    g_hst[bb * HID + j] = h_prev;          // state hand-off (exact fp32)
}

// ---------------------------------------------------------------------------
// Kernel 4: output GEMM chunk (timesteps [t0, t0+TL) of every batch).
// Templated on TL (16/32/64): A-tile 128 rows = (128/TL) batches' segments.
// B (v-tile 256) resident, 2 A-tiles per CTA double-buffered.
// ---------------------------------------------------------------------------
#define SB_BYTES   65536                 // 256 rows x 256B (fp16)
#define SA_BYTES   32768                 // per stage: 128 rows x 256B
#define N_TILES    2
#define SM_TOTAL   (SB_BYTES + N_TILES * SA_BYTES)   // 128 KB

template<int TL>
__device__ __forceinline__ void gemm_load_a(uint32_t sAbuf, int bstart, int t0,
                                            int tid) {
    #pragma unroll
    for (int i = tid; i < 2048; i += 256) {       // 128 rows x 16 chunks
        int row = i >> 4, ch = i & 15;
        int gr = (bstart + row / TL) * TLEN + t0 + (row & (TL - 1));
        uint32_t dst = sAbuf + row * 256 + ((ch ^ (row & 7)) << 4);
        cp16(dst, g_rnn_h + (size_t)gr * HID + ch * 8);
    }
}

template<int TL>
__global__ void __launch_bounds__(256, 1) k_gemm(const float* __restrict__ bd,
                                                 float* __restrict__ out, int t0) {
    extern __shared__ char smem[];
    uint32_t sB  = smem_u32(smem);
    uint32_t sA0 = sB + SB_BYTES;

    int tid  = threadIdx.x;
    int wid  = tid >> 5;
    int lane = tid & 31;
    int v0   = blockIdx.x * 256;
    const int BPT = 128 / TL;               // batches per A-tile
    int bg   = blockIdx.y * (N_TILES * BPT);

    // ---- prologue: B (resident) + A0 in group 0; A1 in group 1 ----
    #pragma unroll
    for (int i = tid; i < 4096; i += 256) {       // B: 256 rows x 16 chunks
        int row = i >> 4, ch = i & 15;
        uint32_t dst = sB + row * 256 + ((ch ^ (row & 7)) << 4);
        cp16(dst, g_wdt_h + (size_t)(v0 + row) * HID + ch * 8);
    }
    gemm_load_a<TL>(sA0, bg, t0, tid);
    CP_COMMIT();
    gemm_load_a<TL>(sA0 + SA_BYTES, bg + BPT, t0, tid);
    CP_COMMIT();

    int wm = wid & 1;          // 2 warps over the 128 A rows (64 each)
    int wn = wid >> 1;         // 4 warps over v (64 each)
    int rA  = ((lane >> 3) & 1) * 8 + (lane & 7);
    int kcA = lane >> 4;
    int rB  = ((lane >> 4) & 1) * 8 + (lane & 7);
    int kcB = (lane >> 3) & 1;
    int lx  = lane & 7;

    #pragma unroll 1
    for (int it = 0; it < N_TILES; it++) {
        if (it == 0) { CP_WAIT(1); } else { CP_WAIT(0); }
        __syncthreads();

        uint32_t sAb = sA0 + it * SA_BYTES;
        int btile = bg + it * BPT;            // first batch of this A-tile

        float c[4][8][4];
        #pragma unroll
        for (int mb = 0; mb < 4; mb++)
            #pragma unroll
            for (int nb = 0; nb < 8; nb++)
                #pragma unroll
                for (int q = 0; q < 4; q++) c[mb][nb][q] = 0.f;

        uint32_t aBase = sAb + (uint32_t)(wm * 64 + rA) * 256;
        uint32_t bBase = sB  + (uint32_t)(wn * 64 + rB) * 256;
        #pragma unroll 1
        for (int ks = 0; ks < 8; ks++) {
            uint32_t a[4][4], b[4][4];
            int kA = (ks * 2 + kcA) ^ lx;
            int kB = (ks * 2 + kcB) ^ lx;
            #pragma unroll
            for (int mb = 0; mb < 4; mb++)
                ldsm_x4(a[mb], aBase + (uint32_t)(mb * 16) * 256 + (kA << 4));
            #pragma unroll
            for (int nb = 0; nb < 4; nb++)
                ldsm_x4(b[nb], bBase + (uint32_t)(nb * 16) * 256 + (kB << 4));
            #pragma unroll
            for (int mb = 0; mb < 4; mb++)
                #pragma unroll
                for (int nbi = 0; nbi < 8; nbi++)
                    mma16816(c[mb][nbi], a[mb],
                             b[nbi >> 1][(nbi & 1) * 2],
                             b[nbi >> 1][(nbi & 1) * 2 + 1]);
        }
        __syncthreads();

        // ---- epilogue: bias + store ----
        #pragma unroll
        for (int nbi = 0; nbi < 8; nbi++) {
            int col = v0 + wn * 64 + nbi * 8 + (lane & 3) * 2;
            if (col < VOCAB) {
                float b0 = bd[col], b1 = bd[col + 1];
                #pragma unroll
                for (int mb = 0; mb < 4; mb++) {
                    int lr0 = wm * 64 + mb * 16;          // local A row of c[..][0]
                    int r = (btile + lr0 / TL) * TLEN + t0 + (lr0 & (TL - 1))
                          + (lane >> 2);
                    float2 lo = make_float2(c[mb][nbi][0] + b0, c[mb][nbi][1] + b1);
                    float2 hi = make_float2(c[mb][nbi][2] + b0, c[mb][nbi][3] + b1);
                    *(float2*)(out + (size_t)r * VOCAB + col) = lo;
                    *(float2*)(out + (size_t)(r + 8) * VOCAB + col) = hi;
                }
            }
        }
    }
}

// ---------------------------------------------------------------------------
// Launch: chunks (32,64,64,64,16,16). s2 = wdt; s4 = embed rest + odd gemm;
// s3 = even gemm. Each gemm gated on eWdt + its scan event.
// ---------------------------------------------------------------------------
#define NCHUNK 6

extern "C" void kernel_launch(void* const* d_in, const int* in_sizes, int n_in,
                              void* d_out, int out_size) {
    const void*  ids = d_in[0];
    const float* emb = (const float*)d_in[1];
    const float* W   = (const float*)d_in[2];
    const float* U   = (const float*)d_in[3];
    const float* b   = (const float*)d_in[4];
    const float* Wd  = (const float*)d_in[5];
    const float* bd  = (const float*)d_in[6];
    float* out = (float*)d_out;

    static cudaStream_t s2 = nullptr, s3 = nullptr, s4 = nullptr;
    static cudaEvent_t eFork = nullptr, eWdt = nullptr,
                       eEr1 = nullptr, eEr2 = nullptr,
                       eS[NCHUNK] = {}, eG3 = nullptr, eG4 = nullptr;
    if (!s2) {
        cudaStreamCreateWithFlags(&s2, cudaStreamNonBlocking);
        cudaStreamCreateWithFlags(&s3, cudaStreamNonBlocking);
        cudaStreamCreateWithFlags(&s4, cudaStreamNonBlocking);
        cudaEventCreateWithFlags(&eFork, cudaEventDisableTiming);
        cudaEventCreateWithFlags(&eWdt,  cudaEventDisableTiming);
        cudaEventCreateWithFlags(&eEr1,  cudaEventDisableTiming);
        cudaEventCreateWithFlags(&eEr2,  cudaEventDisableTiming);
        for (int i = 0; i < NCHUNK; i++)
            cudaEventCreateWithFlags(&eS[i], cudaEventDisableTiming);
        cudaEventCreateWithFlags(&eG3, cudaEventDisableTiming);
        cudaEventCreateWithFlags(&eG4, cudaEventDisableTiming);
        cudaFuncSetAttribute(k_gemm<64>, cudaFuncAttributeMaxDynamicSharedMemorySize, SM_TOTAL);
        cudaFuncSetAttribute(k_gemm<32>, cudaFuncAttributeMaxDynamicSharedMemorySize, SM_TOTAL);
        cudaFuncSetAttribute(k_gemm<16>, cudaFuncAttributeMaxDynamicSharedMemorySize, SM_TOTAL);
    }

    cudaEventRecord(eFork, 0);

    // s2: Wd transpose
    cudaStreamWaitEvent(s2, eFork, 0);
    k_wdt<<<dim3(VPAD / 32, HID / 32), dim3(32, 8), 0, s2>>>(Wd);
    cudaEventRecord(eWdt, s2);

    // main: embed head (t < 32) — gates scan chunk 0
    k_embed<<<BATCH, 256>>>(ids, emb, W, b, 0, 1);

    // s4: embed rest (starts at graph origin)
    cudaStreamWaitEvent(s4, eFork, 0);
    k_embed<<<BATCH * 2, 256, 0, s4>>>(ids, emb, W, b, 32, 2);    // t in [32,96)
    cudaEventRecord(eEr1, s4);
    k_embed<<<BATCH * 5, 256, 0, s4>>>(ids, emb, W, b, 96, 5);    // t in [96,256)
    cudaEventRecord(eEr2, s4);

    // main: scan chunks 32,64,64,64,16,16
    static const int t0s[NCHUNK]  = {0, 32, 96, 160, 224, 240};
    static const int tchs[NCHUNK] = {32, 64, 64, 64, 16, 16};
    for (int q = 0; q < NCHUNK; q++) {
        if (q == 1) cudaStreamWaitEvent(0, eEr1, 0);
        if (q == 2) cudaStreamWaitEvent(0, eEr2, 0);
        k_scan<<<BATCH, HID>>>(U, t0s[q], tchs[q]);
        cudaEventRecord(eS[q], 0);
    }

    // gemm chunks: even on s3, odd on s4; each gated on eWdt + its scan
    cudaStreamWaitEvent(s3, eWdt, 0);
    cudaStreamWaitEvent(s4, eWdt, 0);

    cudaStreamWaitEvent(s3, eS[0], 0);
    k_gemm<32><<<dim3(VPAD / 256, 4), 256, SM_TOTAL, s3>>>(bd, out, t0s[0]);
    cudaStreamWaitEvent(s4, eS[1], 0);
    k_gemm<64><<<dim3(VPAD / 256, 8), 256, SM_TOTAL, s4>>>(bd, out, t0s[1]);
    cudaStreamWaitEvent(s3, eS[2], 0);
    k_gemm<64><<<dim3(VPAD / 256, 8), 256, SM_TOTAL, s3>>>(bd, out, t0s[2]);
    cudaStreamWaitEvent(s4, eS[3], 0);
    k_gemm<64><<<dim3(VPAD / 256, 8), 256, SM_TOTAL, s4>>>(bd, out, t0s[3]);
    cudaStreamWaitEvent(s3, eS[4], 0);
    k_gemm<16><<<dim3(VPAD / 256, 2), 256, SM_TOTAL, s3>>>(bd, out, t0s[4]);
    cudaStreamWaitEvent(s4, eS[5], 0);
    k_gemm<16><<<dim3(VPAD / 256, 2), 256, SM_TOTAL, s4>>>(bd, out, t0s[5]);

    cudaEventRecord(eG3, s3);
    cudaEventRecord(eG4, s4);
    cudaStreamWaitEvent(0, eG3, 0);
    cudaStreamWaitEvent(0, eG4, 0);
}